// round 4
// baseline (speedup 1.0000x reference)
#include <cuda_runtime.h>
#include <cuda_fp16.h>
#include <math.h>

#define NX 128
#define NG 64
#define P  8192
#define T_STEPS 4
#define N_ITER 50
#define KAPPA 0.8f
#define LAMDA 0.9f
#define YITA  0.1f
#define NEG_SLOPE 0.01f

#define NBLK 512
#define CPB  16          // columns per block (P / NBLK)
#define NTHR 256

// Device scratch (static __device__ — the sanctioned path)
__device__ __half g_M16[(size_t)P * P];   // 128 MB fp16 copy of M0
__device__ float g_h[P];
__device__ float g_u[3 * P];              // u_s = p+h from earlier timesteps
__device__ float g_v[3 * P];              // v_s = p-h
__device__ float g_dotpart[3 * NBLK];     // per-block partials of h . u_s
__device__ float g_loss;
__device__ volatile unsigned g_gen;       // grid barrier generation
__device__ unsigned g_count;              // grid barrier arrival count (invariant: 0 between barriers)

__device__ __forceinline__ float f_p(float v) {
    float c = fminf(fmaxf(v, -1.0f), 1.0f);
    return (c >= 0.0f) ? c : NEG_SLOPE * c;
}

// Software grid barrier. All 512 blocks are co-resident (occupancy-proven),
// so spinning is deadlock-free. Values never depend on arrival order.
__device__ __forceinline__ void grid_barrier() {
    __threadfence();            // every thread: publish my writes before arriving
    __syncthreads();
    if (threadIdx.x == 0) {
        unsigned my = g_gen;
        if (atomicAdd(&g_count, 1) == NBLK - 1) {
            g_count = 0;
            __threadfence();
            g_gen = my + 1;     // release
        } else {
            while (g_gen == my) __nanosleep(64);
        }
    }
    __syncthreads();
    __threadfence();
}

// Convert M0 fp32 -> fp16 (runs once per replay)
__global__ void k_convert(const float* __restrict__ M) {
    size_t i = ((size_t)blockIdx.x * blockDim.x + threadIdx.x) * 8;
    const float4* src = (const float4*)(M + i);
    float4 a = src[0];
    float4 b = src[1];
    __half2 h0 = __floats2half2_rn(a.x, a.y);
    __half2 h1 = __floats2half2_rn(a.z, a.w);
    __half2 h2 = __floats2half2_rn(b.x, b.y);
    __half2 h3 = __floats2half2_rn(b.z, b.w);
    uint4 out;
    out.x = *(unsigned*)&h0;
    out.y = *(unsigned*)&h1;
    out.z = *(unsigned*)&h2;
    out.w = *(unsigned*)&h3;
    *(uint4*)(g_M16 + i) = out;
}

// Persistent attractor: 50 iterations of h = f_p(kappa*h + h * (h@M_t))
// with M_t = lam_pow*M0 + sum_s w_s * outer(u_s, v_s) applied analytically.
// Block b owns columns [b*16, b*16+16) across ALL rows. Full h in smem.
__global__ void __launch_bounds__(NTHR, 4)
k_attractor(int nterms, float lam_pow, float w0, float w1, float w2) {
    __shared__ float h_sm[P];           // 32 KB: full h vector
    __shared__ float red[8][2][8];      // per-warp column partial sums
    __shared__ float dred[NTHR];        // dot reduction buffer

    const int b    = blockIdx.x;
    const int tid  = threadIdx.x;
    const int lane = tid & 31;
    const int wid  = tid >> 5;
    const int ch   = tid & 1;           // which 8-col half of the strip
    const int rl   = tid >> 1;          // row lane 0..127
    const int cb0  = b * CPB;

    // Prologue: publish dot partials of the initial h (written by k_init)
    if (nterms > 0 && tid < CPB) {
        int col = cb0 + tid;
        float hv = g_h[col];            // fresh launch: L1 clean
        for (int s = 0; s < nterms; ++s) {
            float w = hv * g_u[s * P + col];
#pragma unroll
            for (int off = 8; off; off >>= 1)
                w += __shfl_xor_sync(0xFFFFu, w, off);
            if (tid == 0) g_dotpart[s * NBLK + b] = w;
        }
    }
    grid_barrier();

    for (int it = 0; it < N_ITER; ++it) {
        // --- global dots of current h (fixed-order tree: deterministic,
        //     every block computes the identical value) ---
        float dots[3] = {0.f, 0.f, 0.f};
        if (nterms > 0) {
            for (int s = 0; s < nterms; ++s) {
                float a = __ldcg(&g_dotpart[s * NBLK + tid]) +
                          __ldcg(&g_dotpart[s * NBLK + NTHR + tid]);
                dred[tid] = a;
                __syncthreads();
                for (int o = 128; o > 0; o >>= 1) {
                    if (tid < o) dred[tid] += dred[tid + o];
                    __syncthreads();
                }
                dots[s] = dred[0];
                __syncthreads();
            }
        }

        // --- reload full h into smem (ldcg: L1 is stale across iterations) ---
        for (int i = tid; i < P / 4; i += NTHR) {
            float4 v4 = __ldcg(((const float4*)g_h) + i);
            ((float4*)h_sm)[i] = v4;
        }
        __syncthreads();

        // --- matvec: 16-col strip over all 8192 rows ---
        const __half* Mp = g_M16 + (size_t)rl * P + cb0 + ch * 8;
        float acc[8];
#pragma unroll
        for (int j = 0; j < 8; ++j) acc[j] = 0.f;
#pragma unroll 8
        for (int k = 0; k < P / 128; ++k) {
            uint4 m = __ldg((const uint4*)(Mp + (size_t)k * 128 * P));
            float hv = h_sm[rl + 128 * k];
            float2 f0 = __half22float2(*(__half2*)&m.x);
            float2 f1 = __half22float2(*(__half2*)&m.y);
            float2 f2 = __half22float2(*(__half2*)&m.z);
            float2 f3 = __half22float2(*(__half2*)&m.w);
            acc[0] = fmaf(hv, f0.x, acc[0]); acc[1] = fmaf(hv, f0.y, acc[1]);
            acc[2] = fmaf(hv, f1.x, acc[2]); acc[3] = fmaf(hv, f1.y, acc[3]);
            acc[4] = fmaf(hv, f2.x, acc[4]); acc[5] = fmaf(hv, f2.y, acc[5]);
            acc[6] = fmaf(hv, f3.x, acc[6]); acc[7] = fmaf(hv, f3.y, acc[7]);
        }
        // reduce across same-parity lanes (fixed xor tree: deterministic)
#pragma unroll
        for (int j = 0; j < 8; ++j) {
#pragma unroll
            for (int off = 2; off < 32; off <<= 1)
                acc[j] += __shfl_xor_sync(0xFFFFFFFFu, acc[j], off);
        }
        if (lane < 2) {
#pragma unroll
            for (int j = 0; j < 8; ++j) red[wid][lane][j] = acc[j];
        }
        __syncthreads();

        // --- final reduce + pointwise update, threads 0..15 ---
        if (tid < CPB) {
            int col = cb0 + tid;
            int chh = tid >> 3, jj = tid & 7;
            float y = 0.f;
#pragma unroll
            for (int w = 0; w < 8; ++w) y += red[w][chh][jj];
            y *= lam_pow;
            if (nterms > 0) y = fmaf(w0 * dots[0], __ldg(&g_v[0 * P + col]), y);
            if (nterms > 1) y = fmaf(w1 * dots[1], __ldg(&g_v[1 * P + col]), y);
            if (nterms > 2) y = fmaf(w2 * dots[2], __ldg(&g_v[2 * P + col]), y);
            float ho = h_sm[col];
            float hn = f_p(KAPPA * ho + ho * y);
            g_h[col] = hn;
            // publish dot partials of the NEW h for next iteration
            if (nterms > 0) {
                for (int s = 0; s < nterms; ++s) {
                    float w = hn * __ldg(&g_u[s * P + col]);
#pragma unroll
                    for (int off = 8; off; off >>= 1)
                        w += __shfl_xor_sync(0xFFFFu, w, off);
                    if (tid == 0) g_dotpart[s * NBLK + b] = w;
                }
            }
        }
        grid_barrier();
    }
}

// Per-step init: h0 = f_p(tile(g_t, NX)); zero loss accumulator at t==0
__global__ void k_init(const float* __restrict__ g, int t) {
    int k = blockIdx.x * 256 + threadIdx.x;
    g_h[k] = f_p(g[t * NG + (k & (NG - 1))]);
    if (t == 0 && k == 0) g_loss = 0.0f;
}

// Per-step finalize: loss += sum |p - h|; store u_t = p+h, v_t = p-h
__global__ void k_final(const float* __restrict__ x, const float* __restrict__ g,
                        int t, float* __restrict__ out) {
    __shared__ float red[256];
    int tid = threadIdx.x;
    float a = 0.0f;
    for (int k = tid; k < P; k += 256) {
        float p = x[t * NX + (k >> 6)] * g[t * NG + (k & (NG - 1))];
        float h = g_h[k];
        if (t < 3) {
            g_u[t * P + k] = p + h;
            g_v[t * P + k] = p - h;
        }
        a += fabsf(p - h);
    }
    red[tid] = a;
    __syncthreads();
    for (int o = 128; o > 0; o >>= 1) {
        if (tid < o) red[tid] += red[tid + o];
        __syncthreads();
    }
    if (tid == 0) {
        g_loss += red[0];
        *out = g_loss;
    }
}

extern "C" void kernel_launch(void* const* d_in, const int* in_sizes, int n_in,
                              void* d_out, int out_size) {
    const float* x = (const float*)d_in[0];   // [4,128]
    const float* g = (const float*)d_in[1];   // [4,64]
    const float* M = (const float*)d_in[2];   // [8192,8192]
    float* out = (float*)d_out;
    (void)in_sizes; (void)n_in; (void)out_size;

    // fp16 copy of M0 (runs each replay: deterministic, graph-capturable)
    k_convert<<<(int)((size_t)P * P / 8 / 256), 256>>>(M);

    for (int t = 0; t < T_STEPS; ++t) {
        k_init<<<P / 256, 256>>>(g, t);

        float lam_pow = 1.0f;
        for (int i = 0; i < t; ++i) lam_pow *= LAMDA;
        float w[3] = {0.0f, 0.0f, 0.0f};
        for (int s = 0; s < t; ++s) {
            float lp = 1.0f;
            for (int i = 0; i < t - 1 - s; ++i) lp *= LAMDA;
            w[s] = YITA * lp;
        }

        k_attractor<<<NBLK, NTHR>>>(t, lam_pow, w[0], w[1], w[2]);

        k_final<<<1, 256>>>(x, g, t, out);
    }
}

// round 5
// speedup vs baseline: 1.0531x; 1.0531x over previous
#include <cuda_runtime.h>
#include <cuda_fp16.h>
#include <math.h>

#define NX 128
#define NG 64
#define P  8192
#define T_STEPS 4
#define N_ITER 50
#define KAPPA 0.8f
#define LAMDA 0.9f
#define YITA  0.1f
#define NEG_SLOPE 0.01f

#define NBLK 128         // blocks; each owns 64 contiguous columns (one 128B line/row)
#define CPB  64          // columns per block
#define NTHR 256

// Device scratch (static __device__ — the sanctioned path)
__device__ __half g_M16[(size_t)P * P];   // 128 MB fp16 copy of M0
__device__ float g_h[P];
__device__ float g_u[3 * P];              // u_s = p+h from earlier timesteps
__device__ float g_v[3 * P];              // v_s = p-h
__device__ float g_dotpart[3 * NBLK];     // per-block partials (dots / loss)
__device__ float g_loss;
__device__ volatile unsigned g_gen;       // grid barrier generation
__device__ unsigned g_count;              // barrier arrivals (0 between barriers)

__device__ __forceinline__ float f_p(float v) {
    float c = fminf(fmaxf(v, -1.0f), 1.0f);
    return (c >= 0.0f) ? c : NEG_SLOPE * c;
}

// Software grid barrier; all NBLK blocks co-resident (128 <= 148 SMs, 1/SM).
__device__ __forceinline__ void grid_barrier() {
    if (threadIdx.x < CPB) __threadfence();   // only tid<64 write globals
    __syncthreads();
    if (threadIdx.x == 0) {
        unsigned my = g_gen;
        if (atomicAdd(&g_count, 1) == NBLK - 1) {
            g_count = 0;
            __threadfence();
            g_gen = my + 1;   // release
        } else {
            while (g_gen == my) __nanosleep(64);
        }
    }
    __syncthreads();
    __threadfence();
}

// Convert M0 fp32 -> fp16 (runs each replay)
__global__ void k_convert(const float* __restrict__ M) {
    size_t i = ((size_t)blockIdx.x * blockDim.x + threadIdx.x) * 8;
    const float4* src = (const float4*)(M + i);
    float4 a = src[0];
    float4 b = src[1];
    __half2 h0 = __floats2half2_rn(a.x, a.y);
    __half2 h1 = __floats2half2_rn(a.z, a.w);
    __half2 h2 = __floats2half2_rn(b.x, b.y);
    __half2 h3 = __floats2half2_rn(b.z, b.w);
    uint4 out;
    out.x = *(unsigned*)&h0;
    out.y = *(unsigned*)&h1;
    out.z = *(unsigned*)&h2;
    out.w = *(unsigned*)&h3;
    *(uint4*)(g_M16 + i) = out;
}

// Persistent per-timestep kernel: init + 50 attractor iterations + loss.
// M_t = lam_pow*M0 + sum_s w_s * outer(u_s, v_s), applied analytically.
// Block b owns columns [b*64, b*64+64); full h staged in smem each iter.
__global__ void __launch_bounds__(NTHR, 1)
k_attractor(const float* __restrict__ x, const float* __restrict__ gin,
            float* __restrict__ out, int t,
            float lam_pow, float w0, float w1, float w2) {
    __shared__ float h_sm[P];          // 32 KB full h
    __shared__ float red[CPB][33];     // padded column partials
    __shared__ float dred[NTHR];

    const int b   = blockIdx.x;
    const int tid = threadIdx.x;
    const int rg  = tid >> 3;          // row group 0..31
    const int cc  = tid & 7;           // col chunk 0..7
    const int cb0 = b * CPB;
    const int nterms = t;

    // ---- init: h0 = f_p(tile(g_t)) computed locally (no global traffic) ----
    for (int k = tid; k < P; k += NTHR)
        h_sm[k] = f_p(gin[t * NG + (k & (NG - 1))]);
    __syncthreads();

    // ---- prologue: publish dot partials of h0 (only t>0) ----
    if (nterms > 0) {
        float pr[3] = {0.f, 0.f, 0.f};
        if (tid < CPB) {
            int col = cb0 + tid;
            float hv = h_sm[col];
            for (int s = 0; s < nterms; ++s) pr[s] = hv * __ldg(&g_u[s * P + col]);
        }
        for (int s = 0; s < nterms; ++s) {
            dred[tid] = (tid < CPB) ? pr[s] : 0.f;
            __syncthreads();
            for (int o = 128; o > 0; o >>= 1) {
                if (tid < o) dred[tid] += dred[tid + o];
                __syncthreads();
            }
            if (tid == 0) g_dotpart[s * NBLK + b] = dred[0];
            __syncthreads();
        }
        grid_barrier();
    }

    float hn_val = 0.f;   // tid<64: this thread's column value of h

    for (int it = 0; it < N_ITER; ++it) {
        // ---- global dots (identical fixed-order tree in every block) ----
        float dots[3] = {0.f, 0.f, 0.f};
        for (int s = 0; s < nterms; ++s) {
            dred[tid] = (tid < NBLK) ? __ldcg(&g_dotpart[s * NBLK + tid]) : 0.f;
            __syncthreads();
            for (int o = 128; o > 0; o >>= 1) {
                if (tid < o) dred[tid] += dred[tid + o];
                __syncthreads();
            }
            dots[s] = dred[0];
            __syncthreads();
        }

        // ---- refresh full h (it==0: already computed locally) ----
        if (it > 0) {
            for (int i = tid; i < P / 4; i += NTHR)
                ((float4*)h_sm)[i] = __ldcg(((const float4*)g_h) + i);
            __syncthreads();
        }

        // ---- matvec: 64-col block, full K; one uint4 (8 cols) per row/thread ----
        const uint4* __restrict__ Mp =
            (const uint4*)(g_M16 + (size_t)rg * P + cb0 + cc * 8);
        float a0=0.f,a1=0.f,a2=0.f,a3=0.f,a4=0.f,a5=0.f,a6=0.f,a7=0.f;
#pragma unroll 8
        for (int k = 0; k < P / 32; ++k) {
            uint4 m = __ldg(Mp);
            Mp += (32 * P) / 8;        // next 32-row step (uint4 stride)
            float hv = h_sm[rg + 32 * k];
            float2 f0 = __half22float2(*(__half2*)&m.x);
            float2 f1 = __half22float2(*(__half2*)&m.y);
            float2 f2 = __half22float2(*(__half2*)&m.z);
            float2 f3 = __half22float2(*(__half2*)&m.w);
            a0 = fmaf(hv, f0.x, a0); a1 = fmaf(hv, f0.y, a1);
            a2 = fmaf(hv, f1.x, a2); a3 = fmaf(hv, f1.y, a3);
            a4 = fmaf(hv, f2.x, a4); a5 = fmaf(hv, f2.y, a5);
            a6 = fmaf(hv, f3.x, a6); a7 = fmaf(hv, f3.y, a7);
        }
        red[cc * 8 + 0][rg] = a0; red[cc * 8 + 1][rg] = a1;
        red[cc * 8 + 2][rg] = a2; red[cc * 8 + 3][rg] = a3;
        red[cc * 8 + 4][rg] = a4; red[cc * 8 + 5][rg] = a5;
        red[cc * 8 + 6][rg] = a6; red[cc * 8 + 7][rg] = a7;
        __syncthreads();

        // ---- column reduce + rank-1 corrections + pointwise update ----
        float pr[3] = {0.f, 0.f, 0.f};
        if (tid < CPB) {
            int col = cb0 + tid;
            float y = 0.f;
#pragma unroll
            for (int g2 = 0; g2 < 32; ++g2) y += red[tid][g2];
            y *= lam_pow;
            if (nterms > 0) y = fmaf(w0 * dots[0], __ldg(&g_v[0 * P + col]), y);
            if (nterms > 1) y = fmaf(w1 * dots[1], __ldg(&g_v[1 * P + col]), y);
            if (nterms > 2) y = fmaf(w2 * dots[2], __ldg(&g_v[2 * P + col]), y);
            float ho = h_sm[col];
            hn_val = f_p(KAPPA * ho + ho * y);
            g_h[col] = hn_val;
            if (nterms > 0 && it < N_ITER - 1) {
                for (int s = 0; s < nterms; ++s)
                    pr[s] = hn_val * __ldg(&g_u[s * P + col]);
            }
        }
        // publish dot partials of new h (not needed after last iteration)
        if (nterms > 0 && it < N_ITER - 1) {
            for (int s = 0; s < nterms; ++s) {
                dred[tid] = (tid < CPB) ? pr[s] : 0.f;
                __syncthreads();
                for (int o = 128; o > 0; o >>= 1) {
                    if (tid < o) dred[tid] += dred[tid + o];
                    __syncthreads();
                }
                if (tid == 0) g_dotpart[s * NBLK + b] = dred[0];
                __syncthreads();
            }
        }
        grid_barrier();
    }

    // ---- epilogue: loss partial, store u/v, block 0 finalizes ----
    float a = 0.f;
    if (tid < CPB) {
        int col = cb0 + tid;
        float p = x[t * NX + (col >> 6)] * gin[t * NG + (col & (NG - 1))];
        float h = hn_val;
        if (t < 3) {
            g_u[t * P + col] = p + h;
            g_v[t * P + col] = p - h;
        }
        a = fabsf(p - h);
    }
    dred[tid] = a;
    __syncthreads();
    for (int o = 128; o > 0; o >>= 1) {
        if (tid < o) dred[tid] += dred[tid + o];
        __syncthreads();
    }
    if (tid == 0) g_dotpart[b] = dred[0];
    grid_barrier();

    if (b == 0) {
        dred[tid] = (tid < NBLK) ? __ldcg(&g_dotpart[tid]) : 0.f;
        __syncthreads();
        for (int o = 128; o > 0; o >>= 1) {
            if (tid < o) dred[tid] += dred[tid + o];
            __syncthreads();
        }
        if (tid == 0) {
            float L = (t == 0 ? 0.f : g_loss) + dred[0];
            g_loss = L;
            *out = L;
        }
    }
}

extern "C" void kernel_launch(void* const* d_in, const int* in_sizes, int n_in,
                              void* d_out, int out_size) {
    const float* x = (const float*)d_in[0];   // [4,128]
    const float* g = (const float*)d_in[1];   // [4,64]
    const float* M = (const float*)d_in[2];   // [8192,8192]
    float* out = (float*)d_out;
    (void)in_sizes; (void)n_in; (void)out_size;

    k_convert<<<(int)((size_t)P * P / 8 / 256), 256>>>(M);

    for (int t = 0; t < T_STEPS; ++t) {
        float lam_pow = 1.0f;
        for (int i = 0; i < t; ++i) lam_pow *= LAMDA;
        float w[3] = {0.0f, 0.0f, 0.0f};
        for (int s = 0; s < t; ++s) {
            float lp = 1.0f;
            for (int i = 0; i < t - 1 - s; ++i) lp *= LAMDA;
            w[s] = YITA * lp;
        }
        k_attractor<<<NBLK, NTHR>>>(x, g, out, t, lam_pow, w[0], w[1], w[2]);
    }
}

// round 6
// speedup vs baseline: 1.4767x; 1.4022x over previous
#include <cuda_runtime.h>
#include <cuda_fp16.h>
#include <math.h>

#define NX 128
#define NG 64
#define P  8192
#define T_STEPS 4
#define N_ITER 50
#define KAPPA 0.8f
#define LAMDA 0.9f
#define YITA  0.1f
#define NEG_SLOPE 0.01f

#define NBLK 128         // blocks; each owns 64 contiguous columns
#define CPB  64          // columns per block (64 cols * 2B = one 128B line/row)
#define NTHR 1024        // 32 warps/SM for MLP

// Device scratch (static __device__ — the sanctioned path)
__device__ __half g_M16[(size_t)P * P];   // 128 MB fp16 copy of M0
__device__ float g_h[P];
__device__ float g_u[3 * P];              // u_s = p+h from earlier timesteps
__device__ float g_v[3 * P];              // v_s = p-h
__device__ float g_dotpart[3 * NBLK];     // per-block partials (dots / loss)
__device__ float g_loss;
__device__ volatile unsigned g_gen;       // grid barrier generation
__device__ unsigned g_count;              // barrier arrivals (0 between barriers)

__device__ __forceinline__ float f_p(float v) {
    float c = fminf(fmaxf(v, -1.0f), 1.0f);
    return (c >= 0.0f) ? c : NEG_SLOPE * c;
}

// Software grid barrier; all NBLK blocks co-resident (128 <= 148 SMs, 1/SM).
__device__ __forceinline__ void grid_barrier() {
    if (threadIdx.x < CPB) __threadfence();   // only tid<64 write globals
    __syncthreads();
    if (threadIdx.x == 0) {
        unsigned my = g_gen;
        if (atomicAdd(&g_count, 1) == NBLK - 1) {
            g_count = 0;
            __threadfence();
            g_gen = my + 1;   // release
        } else {
            while (g_gen == my) __nanosleep(64);
        }
    }
    __syncthreads();
    __threadfence();
}

// Convert M0 fp32 -> fp16 (runs each replay)
__global__ void k_convert(const float* __restrict__ M) {
    size_t i = ((size_t)blockIdx.x * blockDim.x + threadIdx.x) * 8;
    const float4* src = (const float4*)(M + i);
    float4 a = src[0];
    float4 b = src[1];
    __half2 h0 = __floats2half2_rn(a.x, a.y);
    __half2 h1 = __floats2half2_rn(a.z, a.w);
    __half2 h2 = __floats2half2_rn(b.x, b.y);
    __half2 h3 = __floats2half2_rn(b.z, b.w);
    uint4 out;
    out.x = *(unsigned*)&h0;
    out.y = *(unsigned*)&h1;
    out.z = *(unsigned*)&h2;
    out.w = *(unsigned*)&h3;
    *(uint4*)(g_M16 + i) = out;
}

// Persistent per-timestep kernel: init + 50 attractor iterations + loss.
// M_t = lam_pow*M0 + sum_s w_s * outer(u_s, v_s), applied analytically.
// Block b owns columns [b*64, b*64+64); full h staged in smem each iter.
// Thread (rg = tid>>3, cc = tid&7): rows rg+128k, cols cb0+cc*8..+8.
__global__ void __launch_bounds__(NTHR, 1)
k_attractor(const float* __restrict__ x, const float* __restrict__ gin,
            float* __restrict__ out, int t,
            float lam_pow, float w0, float w1, float w2) {
    __shared__ float h_sm[P];          // 32 KB full h
    __shared__ float red[CPB][33];     // red[col][warp] partials, padded
    __shared__ float dsum[3][4];       // dot reduce: 4 warp sums per term
    __shared__ float psm[3][2];        // publish reduce: 2 warp sums per term

    const int b    = blockIdx.x;
    const int tid  = threadIdx.x;
    const int lane = tid & 31;
    const int wid  = tid >> 5;         // 0..31
    const int rg   = tid >> 3;         // row group 0..127
    const int cc   = tid & 7;          // col chunk 0..7
    const int cb0  = b * CPB;
    const int nterms = t;

    // ---- init: h0 = f_p(tile(g_t)) computed locally (no global traffic) ----
    for (int k = tid; k < P; k += NTHR)
        h_sm[k] = f_p(gin[t * NG + (k & (NG - 1))]);
    __syncthreads();

    // ---- prologue: publish dot partials of h0 (only t>0) ----
    if (nterms > 0) {
        if (tid < CPB) {
            int col = cb0 + tid;
            float hv = h_sm[col];
            for (int s = 0; s < nterms; ++s) {
                float w = hv * __ldg(&g_u[s * P + col]);
#pragma unroll
                for (int off = 16; off; off >>= 1)
                    w += __shfl_xor_sync(0xFFFFFFFFu, w, off);
                if (lane == 0) psm[s][wid] = w;
            }
        }
        __syncthreads();
        if (tid == 0)
            for (int s = 0; s < nterms; ++s)
                g_dotpart[s * NBLK + b] = psm[s][0] + psm[s][1];
        grid_barrier();
    }

    float hn_val = 0.f;   // tid<64: this thread's column value of h

    for (int it = 0; it < N_ITER; ++it) {
        // ---- global dots: 128 partials -> 4 warp sums -> scalar (all blocks
        //      compute the identical fixed-order value) ----
        if (nterms > 0 && tid < NBLK) {
            for (int s = 0; s < nterms; ++s) {
                float a = __ldcg(&g_dotpart[s * NBLK + tid]);
#pragma unroll
                for (int off = 16; off; off >>= 1)
                    a += __shfl_xor_sync(0xFFFFFFFFu, a, off);
                if (lane == 0) dsum[s][wid] = a;
            }
        }

        // ---- refresh full h (it==0: already computed locally) ----
        if (it > 0) {
            for (int i = tid; i < P / 4; i += NTHR)
                ((float4*)h_sm)[i] = __ldcg(((const float4*)g_h) + i);
        }
        __syncthreads();

        float dots[3] = {0.f, 0.f, 0.f};
        for (int s = 0; s < nterms; ++s)
            dots[s] = ((dsum[s][0] + dsum[s][1]) + dsum[s][2]) + dsum[s][3];

        // ---- matvec: 64 rows/thread, one uint4 (8 cols) per row ----
        const uint4* __restrict__ Mp =
            (const uint4*)(g_M16 + (size_t)rg * P + cb0 + cc * 8);
        float a0=0.f,a1=0.f,a2=0.f,a3=0.f,a4=0.f,a5=0.f,a6=0.f,a7=0.f;
#pragma unroll 8
        for (int k = 0; k < P / 128; ++k) {
            uint4 m = __ldg(Mp);
            Mp += (128 * P) / 8;       // next 128-row step (uint4 stride)
            float hv = h_sm[rg + 128 * k];
            float2 f0 = __half22float2(*(__half2*)&m.x);
            float2 f1 = __half22float2(*(__half2*)&m.y);
            float2 f2 = __half22float2(*(__half2*)&m.z);
            float2 f3 = __half22float2(*(__half2*)&m.w);
            a0 = fmaf(hv, f0.x, a0); a1 = fmaf(hv, f0.y, a1);
            a2 = fmaf(hv, f1.x, a2); a3 = fmaf(hv, f1.y, a3);
            a4 = fmaf(hv, f2.x, a4); a5 = fmaf(hv, f2.y, a5);
            a6 = fmaf(hv, f3.x, a6); a7 = fmaf(hv, f3.y, a7);
        }
        // warp reduce over the 4 rg values within this warp (lanes with equal
        // cc combine; fixed xor order -> deterministic). Lanes 0..7 survive.
#pragma unroll
        for (int off = 8; off < 32; off <<= 1) {
            a0 += __shfl_xor_sync(0xFFFFFFFFu, a0, off);
            a1 += __shfl_xor_sync(0xFFFFFFFFu, a1, off);
            a2 += __shfl_xor_sync(0xFFFFFFFFu, a2, off);
            a3 += __shfl_xor_sync(0xFFFFFFFFu, a3, off);
            a4 += __shfl_xor_sync(0xFFFFFFFFu, a4, off);
            a5 += __shfl_xor_sync(0xFFFFFFFFu, a5, off);
            a6 += __shfl_xor_sync(0xFFFFFFFFu, a6, off);
            a7 += __shfl_xor_sync(0xFFFFFFFFu, a7, off);
        }
        if (lane < 8) {
            int c0 = lane * 8;
            red[c0 + 0][wid] = a0; red[c0 + 1][wid] = a1;
            red[c0 + 2][wid] = a2; red[c0 + 3][wid] = a3;
            red[c0 + 4][wid] = a4; red[c0 + 5][wid] = a5;
            red[c0 + 6][wid] = a6; red[c0 + 7][wid] = a7;
        }
        __syncthreads();

        // ---- column reduce + rank-1 corrections + pointwise update ----
        if (tid < CPB) {
            int col = cb0 + tid;
            float y = 0.f;
#pragma unroll
            for (int w = 0; w < 32; ++w) y += red[tid][w];
            y *= lam_pow;
            if (nterms > 0) y = fmaf(w0 * dots[0], __ldg(&g_v[0 * P + col]), y);
            if (nterms > 1) y = fmaf(w1 * dots[1], __ldg(&g_v[1 * P + col]), y);
            if (nterms > 2) y = fmaf(w2 * dots[2], __ldg(&g_v[2 * P + col]), y);
            float ho = h_sm[col];
            hn_val = f_p(KAPPA * ho + ho * y);
            g_h[col] = hn_val;
            // publish dot partials of new h (skip after last iteration)
            if (nterms > 0 && it < N_ITER - 1) {
                for (int s = 0; s < nterms; ++s) {
                    float w = hn_val * __ldg(&g_u[s * P + col]);
#pragma unroll
                    for (int off = 16; off; off >>= 1)
                        w += __shfl_xor_sync(0xFFFFFFFFu, w, off);
                    if (lane == 0) psm[s][wid] = w;
                }
            }
        }
        if (nterms > 0 && it < N_ITER - 1) {
            __syncthreads();
            if (tid == 0)
                for (int s = 0; s < nterms; ++s)
                    g_dotpart[s * NBLK + b] = psm[s][0] + psm[s][1];
        }
        grid_barrier();
    }

    // ---- epilogue: loss partial, store u/v, block 0 finalizes ----
    if (tid < CPB) {
        int col = cb0 + tid;
        float p = x[t * NX + (col >> 6)] * gin[t * NG + (col & (NG - 1))];
        float h = hn_val;
        if (t < 3) {
            g_u[t * P + col] = p + h;
            g_v[t * P + col] = p - h;
        }
        float a = fabsf(p - h);
#pragma unroll
        for (int off = 16; off; off >>= 1)
            a += __shfl_xor_sync(0xFFFFFFFFu, a, off);
        if (lane == 0) psm[0][wid] = a;
    }
    __syncthreads();
    if (tid == 0) g_dotpart[b] = psm[0][0] + psm[0][1];
    grid_barrier();

    if (b == 0) {
        if (tid < NBLK) {
            float a = __ldcg(&g_dotpart[tid]);
#pragma unroll
            for (int off = 16; off; off >>= 1)
                a += __shfl_xor_sync(0xFFFFFFFFu, a, off);
            if (lane == 0) dsum[0][wid] = a;
        }
        __syncthreads();
        if (tid == 0) {
            float L = (t == 0 ? 0.f : g_loss) +
                      (((dsum[0][0] + dsum[0][1]) + dsum[0][2]) + dsum[0][3]);
            g_loss = L;
            *out = L;
        }
    }
}

extern "C" void kernel_launch(void* const* d_in, const int* in_sizes, int n_in,
                              void* d_out, int out_size) {
    const float* x = (const float*)d_in[0];   // [4,128]
    const float* g = (const float*)d_in[1];   // [4,64]
    const float* M = (const float*)d_in[2];   // [8192,8192]
    float* out = (float*)d_out;
    (void)in_sizes; (void)n_in; (void)out_size;

    k_convert<<<(int)((size_t)P * P / 8 / 256), 256>>>(M);

    for (int t = 0; t < T_STEPS; ++t) {
        float lam_pow = 1.0f;
        for (int i = 0; i < t; ++i) lam_pow *= LAMDA;
        float w[3] = {0.0f, 0.0f, 0.0f};
        for (int s = 0; s < t; ++s) {
            float lp = 1.0f;
            for (int i = 0; i < t - 1 - s; ++i) lp *= LAMDA;
            w[s] = YITA * lp;
        }
        k_attractor<<<NBLK, NTHR>>>(x, g, out, t, lam_pow, w[0], w[1], w[2]);
    }
}